// round 13
// baseline (speedup 1.0000x reference)
#include <cuda_runtime.h>

#define IMG_H 512
#define IMG_W 512
#define OUT_H 502
#define OUT_W 502
#define N_IMG 48
#define N_PIX (N_IMG * IMG_H * IMG_W)
#define N_OUT_D 12096192.0
#define TX 32
#define TY 56
#define H_REAL 66           // TY + 10 rows of horizontal results
#define HQ_W 132            // 32 cols x 4 interleave + 4 pad (row stride 528B)
#define GRID_X 16
#define GRID_Y 9            // 9 * 56 = 504 >= 502
#define TOTAL_BLOCKS (GRID_X * GRID_Y * N_IMG)   // 6912
#define H_ITEMS (H_REAL * 8)                     // 528 horizontal work items

__device__ double gSum = 0.0;
__device__ unsigned int gCount = 0u;
__device__ unsigned int gMaxKey = 0u;
__device__ unsigned int gMinKey = 0xFFFFFFFFu;

__device__ __forceinline__ unsigned int fkey(float f) {
    unsigned int u = __float_as_uint(f);
    return (u & 0x80000000u) ? ~u : (u | 0x80000000u);
}
__device__ __forceinline__ float funkey(unsigned int u) {
    return __uint_as_float((u & 0x80000000u) ? (u ^ 0x80000000u) : ~u);
}

__global__ __launch_bounds__(256) void k_minmax(const float* __restrict__ x, int n4) {
    cudaTriggerProgrammaticLaunchCompletion();

    float vmin = 3.4e38f, vmax = -3.4e38f;
    int idx = blockIdx.x * blockDim.x + threadIdx.x;
    int stride = gridDim.x * blockDim.x;
    const float4* x4 = (const float4*)x;
    for (int i = idx; i < n4; i += stride) {
        float4 v = x4[i];
        vmin = fminf(vmin, fminf(fminf(v.x, v.y), fminf(v.z, v.w)));
        vmax = fmaxf(vmax, fmaxf(fmaxf(v.x, v.y), fmaxf(v.z, v.w)));
    }
    #pragma unroll
    for (int o = 16; o; o >>= 1) {
        vmin = fminf(vmin, __shfl_xor_sync(0xffffffffu, vmin, o));
        vmax = fmaxf(vmax, __shfl_xor_sync(0xffffffffu, vmax, o));
    }
    __shared__ float smin[8], smax[8];
    int lane = threadIdx.x & 31, wid = threadIdx.x >> 5;
    if (lane == 0) { smin[wid] = vmin; smax[wid] = vmax; }
    __syncthreads();
    if (threadIdx.x == 0) {
        float bmin = smin[0], bmax = smax[0];
        #pragma unroll
        for (int i = 1; i < 8; i++) {
            bmin = fminf(bmin, smin[i]);
            bmax = fmaxf(bmax, smax[i]);
        }
        atomicMax(&gMaxKey, fkey(bmax));
        atomicMin(&gMinKey, fkey(bmin));
    }
}

// 4-conv reformulation: with s = p+t, d = p-t,
//   S = conv(s), D = conv(d), A = conv(s*s), B = conv(d*d)
//   mu1^2+mu2^2 = (S^2+D^2)/2      mu1*mu2 = (S^2-D^2)/4
//   E11+E22     = (A+B)/2          E12     = (A-B)/4
// which is everything the SSIM map needs.
__global__ __launch_bounds__(256, 4) void k_ssim(const float* __restrict__ P,
                                                 const float* __restrict__ T,
                                                 float* __restrict__ out) {
    constexpr float W[11] = {
        0.00102837f, 0.00759869f, 0.03600077f, 0.10936070f, 0.21300560f,
        0.26601173f,
        0.21300560f, 0.10936070f, 0.03600077f, 0.00759869f, 0.00102837f
    };

    __shared__ float hq[H_REAL][HQ_W];   // interleaved (S, D, A, B) per column
    __shared__ float wsum[8];

    const int img = blockIdx.z;
    const int ox0 = blockIdx.x * TX;
    const int oy0 = blockIdx.y * TY;
    const float* __restrict__ p = P + img * (IMG_H * IMG_W);
    const float* __restrict__ t = T + img * (IMG_H * IMG_W);
    const int tid = threadIdx.x;
    const int tx = tid & 31, ty8 = tid >> 5;

    // ---- horizontal 11-tap pass: 66 rows x 8 col-groups = 528 items ----
    #pragma unroll
    for (int it = 0; it < 3; it++) {
        const int item = tid + (it << 8);
        if (item < H_ITEMS) {
            const int r = item >> 3;             // 0..65
            const int c0 = (item & 7) << 2;      // 0,4,...,28
            const int gr = min(oy0 + r, IMG_H - 1);   // clamped rows feed only masked outputs
            const float* prow = p + gr * IMG_W;
            const float* trow = t + gr * IMG_W;

            float4 qp[4], qt[4];
            #pragma unroll
            for (int ch = 0; ch < 4; ch++) {
                int gc = min(ox0 + c0 + (ch << 2), IMG_W - 4);  // clamped: feeds only masked outputs
                qp[ch] = *reinterpret_cast<const float4*>(prow + gc);
                qt[ch] = *reinterpret_cast<const float4*>(trow + gc);
            }

            float aS[4] = {0.f, 0.f, 0.f, 0.f};
            float aD[4] = {0.f, 0.f, 0.f, 0.f};
            float aA[4] = {0.f, 0.f, 0.f, 0.f};
            float aB[4] = {0.f, 0.f, 0.f, 0.f};
            #pragma unroll
            for (int ch = 0; ch < 4; ch++) {
                float vpc[4] = {qp[ch].x, qp[ch].y, qp[ch].z, qp[ch].w};
                float vtc[4] = {qt[ch].x, qt[ch].y, qt[ch].z, qt[ch].w};
                #pragma unroll
                for (int jv = 0; jv < 4; jv++) {
                    const int j = (ch << 2) + jv;
                    if (j < 14) {
                        float s = vpc[jv] + vtc[jv];
                        float d = vpc[jv] - vtc[jv];
                        float ss = s * s;
                        float dd = d * d;
                        #pragma unroll
                        for (int u = 0; u < 4; u++) {
                            const int k = j - u;
                            if (k >= 0 && k < 11) {
                                aS[u] = fmaf(s,  W[k], aS[u]);
                                aD[u] = fmaf(d,  W[k], aD[u]);
                                aA[u] = fmaf(ss, W[k], aA[u]);
                                aB[u] = fmaf(dd, W[k], aB[u]);
                            }
                        }
                    }
                }
            }
            #pragma unroll
            for (int u = 0; u < 4; u++)
                *reinterpret_cast<float4*>(&hq[r][4 * (c0 + u)]) =
                    make_float4(aS[u], aD[u], aA[u], aB[u]);
        }
    }
    __syncthreads();

    // ---- vertical 11-tap pass: 7 consecutive rows per thread, one LDS.128 per row ----
    const int r0 = ty8 * 7;   // 0,7,...,49; 8x7 = 56 = TY exact
    float vS[7] = {0.f, 0.f, 0.f, 0.f, 0.f, 0.f, 0.f};
    float vD[7] = {0.f, 0.f, 0.f, 0.f, 0.f, 0.f, 0.f};
    float vA[7] = {0.f, 0.f, 0.f, 0.f, 0.f, 0.f, 0.f};
    float vB[7] = {0.f, 0.f, 0.f, 0.f, 0.f, 0.f, 0.f};
    const float4* cq = reinterpret_cast<const float4*>(&hq[r0][4 * tx]);
    #pragma unroll
    for (int i = 0; i < 17; i++) {
        float4 q = cq[i * (HQ_W / 4)];
        #pragma unroll
        for (int u = 0; u < 7; u++) {
            const int k = i - u;
            if (k >= 0 && k < 11) {
                vS[u] = fmaf(q.x, W[k], vS[u]);
                vD[u] = fmaf(q.y, W[k], vD[u]);
                vA[u] = fmaf(q.z, W[k], vA[u]);
                vB[u] = fmaf(q.w, W[k], vB[u]);
            }
        }
    }

    // ---- wait for k_minmax completion ----
    cudaGridDependencySynchronize();
    const float L = funkey(*reinterpret_cast<volatile unsigned int*>(&gMaxKey)) -
                    funkey(*reinterpret_cast<volatile unsigned int*>(&gMinKey));
    const float C1 = (0.01f * L) * (0.01f * L);
    const float C2 = (0.03f * L) * (0.03f * L);

    float localsum = 0.f;
    const int ox = ox0 + tx;
    #pragma unroll
    for (int u = 0; u < 7; u++) {
        int oy = oy0 + r0 + u;
        if (oy < OUT_H && ox < OUT_W) {
            float SS = vS[u] * vS[u];
            float DD = vD[u] * vD[u];
            float musq = 0.5f * (SS + DD);          // mu1^2 + mu2^2
            float mu12 = 0.25f * (SS - DD);         // mu1 * mu2
            float esum = 0.5f * (vA[u] + vB[u]);    // E11 + E22
            float e12  = 0.25f * (vA[u] - vB[u]);   // E12
            float s12 = e12 - mu12;                 // sigma12
            float v2 = esum - musq + C2;            // sigma1^2 + sigma2^2 + C2
            float num = (2.f * mu12 + C1) * (2.f * s12 + C2);
            float den = (musq + C1) * v2;
            localsum += __fdividef(num, den);
        }
    }

    // ---- block reduce, double atomic accumulate, last block finalizes ----
    #pragma unroll
    for (int o = 16; o; o >>= 1)
        localsum += __shfl_xor_sync(0xffffffffu, localsum, o);
    if ((tid & 31) == 0) wsum[tid >> 5] = localsum;
    __syncthreads();
    if (tid == 0) {
        float s = 0.f;
        #pragma unroll
        for (int i = 0; i < 8; i++) s += wsum[i];
        atomicAdd(&gSum, (double)s);
        __threadfence();
        unsigned int old = atomicAdd(&gCount, 1u);
        if (old == TOTAL_BLOCKS - 1) {
            double v = atomicAdd(&gSum, 0.0);
            out[0] = (float)(-v / N_OUT_D);
            gSum = 0.0;
            gCount = 0u;
            gMaxKey = 0u;
            gMinKey = 0xFFFFFFFFu;
        }
    }
}

extern "C" void kernel_launch(void* const* d_in, const int* in_sizes, int n_in,
                              void* d_out, int out_size) {
    const float* y_pred = (const float*)d_in[0];
    const float* y_true = (const float*)d_in[1];
    float* out = (float*)d_out;

    k_minmax<<<1024, 256>>>(y_pred, N_PIX / 4);

    cudaLaunchConfig_t cfg = {};
    cfg.gridDim = dim3(GRID_X, GRID_Y, N_IMG);
    cfg.blockDim = dim3(256, 1, 1);
    cfg.dynamicSmemBytes = 0;
    cudaLaunchAttribute attr[1];
    attr[0].id = cudaLaunchAttributeProgrammaticStreamSerialization;
    attr[0].val.programmaticStreamSerializationAllowed = 1;
    cfg.attrs = attr;
    cfg.numAttrs = 1;
    cudaLaunchKernelEx(&cfg, k_ssim, y_pred, y_true, out);
}

// round 14
// speedup vs baseline: 1.0933x; 1.0933x over previous
#include <cuda_runtime.h>

#define IMG_H 512
#define IMG_W 512
#define OUT_H 502
#define OUT_W 502
#define N_IMG 48
#define N_PIX (N_IMG * IMG_H * IMG_W)
#define N_OUT_D 12096192.0
#define TX 32
#define TY 56
#define H_REAL 66           // TY + 10 rows of horizontal results
#define HQ_W 132            // 32 cols x 4 interleave + 4 pad (row stride 528B)
#define GRID_X 16
#define GRID_Y 9            // 9 * 56 = 504 >= 502
#define TOTAL_BLOCKS (GRID_X * GRID_Y * N_IMG)   // 6912
#define H_ITEMS (H_REAL * 8)                     // 528 horizontal work items

__device__ double gSum = 0.0;
__device__ unsigned int gCount = 0u;
__device__ unsigned int gMaxKey = 0u;
__device__ unsigned int gMinKey = 0xFFFFFFFFu;

__device__ __forceinline__ unsigned int fkey(float f) {
    unsigned int u = __float_as_uint(f);
    return (u & 0x80000000u) ? ~u : (u | 0x80000000u);
}
__device__ __forceinline__ float funkey(unsigned int u) {
    return __uint_as_float((u & 0x80000000u) ? (u ^ 0x80000000u) : ~u);
}

__global__ __launch_bounds__(256) void k_minmax(const float* __restrict__ x, int n4) {
    cudaTriggerProgrammaticLaunchCompletion();

    float vmin = 3.4e38f, vmax = -3.4e38f;
    int idx = blockIdx.x * blockDim.x + threadIdx.x;
    int stride = gridDim.x * blockDim.x;
    const float4* x4 = (const float4*)x;
    for (int i = idx; i < n4; i += stride) {
        float4 v = x4[i];
        vmin = fminf(vmin, fminf(fminf(v.x, v.y), fminf(v.z, v.w)));
        vmax = fmaxf(vmax, fmaxf(fmaxf(v.x, v.y), fmaxf(v.z, v.w)));
    }
    #pragma unroll
    for (int o = 16; o; o >>= 1) {
        vmin = fminf(vmin, __shfl_xor_sync(0xffffffffu, vmin, o));
        vmax = fmaxf(vmax, __shfl_xor_sync(0xffffffffu, vmax, o));
    }
    __shared__ float smin[8], smax[8];
    int lane = threadIdx.x & 31, wid = threadIdx.x >> 5;
    if (lane == 0) { smin[wid] = vmin; smax[wid] = vmax; }
    __syncthreads();
    if (threadIdx.x == 0) {
        float bmin = smin[0], bmax = smax[0];
        #pragma unroll
        for (int i = 1; i < 8; i++) {
            bmin = fminf(bmin, smin[i]);
            bmax = fmaxf(bmax, smax[i]);
        }
        atomicMax(&gMaxKey, fkey(bmax));
        atomicMin(&gMinKey, fkey(bmin));
    }
}

// 4-conv reformulation (s = p+t, d = p-t); 5 blocks/SM for latency hiding.
__global__ __launch_bounds__(256, 5) void k_ssim(const float* __restrict__ P,
                                                 const float* __restrict__ T,
                                                 float* __restrict__ out) {
    constexpr float W[11] = {
        0.00102837f, 0.00759869f, 0.03600077f, 0.10936070f, 0.21300560f,
        0.26601173f,
        0.21300560f, 0.10936070f, 0.03600077f, 0.00759869f, 0.00102837f
    };

    __shared__ float hq[H_REAL][HQ_W];   // interleaved (S, D, A, B) per column
    __shared__ float wsum[8];

    const int img = blockIdx.z;
    const int ox0 = blockIdx.x * TX;
    const int oy0 = blockIdx.y * TY;
    const float* __restrict__ p = P + img * (IMG_H * IMG_W);
    const float* __restrict__ t = T + img * (IMG_H * IMG_W);
    const int tid = threadIdx.x;
    const int tx = tid & 31, ty8 = tid >> 5;

    // ---- horizontal 11-tap pass: 66 rows x 8 col-groups = 528 items ----
    #pragma unroll
    for (int it = 0; it < 3; it++) {
        const int item = tid + (it << 8);
        if (item < H_ITEMS) {
            const int r = item >> 3;             // 0..65
            const int c0 = (item & 7) << 2;      // 0,4,...,28
            const int gr = min(oy0 + r, IMG_H - 1);   // clamped rows feed only masked outputs
            const float* prow = p + gr * IMG_W;
            const float* trow = t + gr * IMG_W;

            float aS[4] = {0.f, 0.f, 0.f, 0.f};
            float aD[4] = {0.f, 0.f, 0.f, 0.f};
            float aA[4] = {0.f, 0.f, 0.f, 0.f};
            float aB[4] = {0.f, 0.f, 0.f, 0.f};
            // process chunk-by-chunk to bound live registers (2 float4 in flight)
            #pragma unroll
            for (int ch = 0; ch < 4; ch++) {
                int gc = min(ox0 + c0 + (ch << 2), IMG_W - 4);  // clamped: feeds masked outputs only
                float4 qp = *reinterpret_cast<const float4*>(prow + gc);
                float4 qt = *reinterpret_cast<const float4*>(trow + gc);
                float vpc[4] = {qp.x, qp.y, qp.z, qp.w};
                float vtc[4] = {qt.x, qt.y, qt.z, qt.w};
                #pragma unroll
                for (int jv = 0; jv < 4; jv++) {
                    const int j = (ch << 2) + jv;
                    if (j < 14) {
                        float s = vpc[jv] + vtc[jv];
                        float d = vpc[jv] - vtc[jv];
                        float ss = s * s;
                        float dd = d * d;
                        #pragma unroll
                        for (int u = 0; u < 4; u++) {
                            const int k = j - u;
                            if (k >= 0 && k < 11) {
                                aS[u] = fmaf(s,  W[k], aS[u]);
                                aD[u] = fmaf(d,  W[k], aD[u]);
                                aA[u] = fmaf(ss, W[k], aA[u]);
                                aB[u] = fmaf(dd, W[k], aB[u]);
                            }
                        }
                    }
                }
            }
            #pragma unroll
            for (int u = 0; u < 4; u++)
                *reinterpret_cast<float4*>(&hq[r][4 * (c0 + u)]) =
                    make_float4(aS[u], aD[u], aA[u], aB[u]);
        }
    }
    __syncthreads();

    // ---- vertical 11-tap pass: 7 consecutive rows per thread, one LDS.128 per row ----
    const int r0 = ty8 * 7;   // 0,7,...,49; 8x7 = 56 = TY exact
    float vS[7] = {0.f, 0.f, 0.f, 0.f, 0.f, 0.f, 0.f};
    float vD[7] = {0.f, 0.f, 0.f, 0.f, 0.f, 0.f, 0.f};
    float vA[7] = {0.f, 0.f, 0.f, 0.f, 0.f, 0.f, 0.f};
    float vB[7] = {0.f, 0.f, 0.f, 0.f, 0.f, 0.f, 0.f};
    const float4* cq = reinterpret_cast<const float4*>(&hq[r0][4 * tx]);
    #pragma unroll
    for (int i = 0; i < 17; i++) {
        float4 q = cq[i * (HQ_W / 4)];
        #pragma unroll
        for (int u = 0; u < 7; u++) {
            const int k = i - u;
            if (k >= 0 && k < 11) {
                vS[u] = fmaf(q.x, W[k], vS[u]);
                vD[u] = fmaf(q.y, W[k], vD[u]);
                vA[u] = fmaf(q.z, W[k], vA[u]);
                vB[u] = fmaf(q.w, W[k], vB[u]);
            }
        }
    }

    // ---- wait for k_minmax completion ----
    cudaGridDependencySynchronize();
    const float L = funkey(*reinterpret_cast<volatile unsigned int*>(&gMaxKey)) -
                    funkey(*reinterpret_cast<volatile unsigned int*>(&gMinKey));
    const float C1 = (0.01f * L) * (0.01f * L);
    const float C2 = (0.03f * L) * (0.03f * L);

    float localsum = 0.f;
    const int ox = ox0 + tx;
    #pragma unroll
    for (int u = 0; u < 7; u++) {
        int oy = oy0 + r0 + u;
        if (oy < OUT_H && ox < OUT_W) {
            float SS = vS[u] * vS[u];
            float DD = vD[u] * vD[u];
            float musq = 0.5f * (SS + DD);          // mu1^2 + mu2^2
            float mu12 = 0.25f * (SS - DD);         // mu1 * mu2
            float esum = 0.5f * (vA[u] + vB[u]);    // E11 + E22
            float e12  = 0.25f * (vA[u] - vB[u]);   // E12
            float s12 = e12 - mu12;                 // sigma12
            float v2 = esum - musq + C2;            // sigma1^2 + sigma2^2 + C2
            float num = (2.f * mu12 + C1) * (2.f * s12 + C2);
            float den = (musq + C1) * v2;
            localsum += __fdividef(num, den);
        }
    }

    // ---- block reduce, double atomic accumulate, last block finalizes ----
    #pragma unroll
    for (int o = 16; o; o >>= 1)
        localsum += __shfl_xor_sync(0xffffffffu, localsum, o);
    if ((tid & 31) == 0) wsum[tid >> 5] = localsum;
    __syncthreads();
    if (tid == 0) {
        float s = 0.f;
        #pragma unroll
        for (int i = 0; i < 8; i++) s += wsum[i];
        atomicAdd(&gSum, (double)s);
        __threadfence();
        unsigned int old = atomicAdd(&gCount, 1u);
        if (old == TOTAL_BLOCKS - 1) {
            double v = atomicAdd(&gSum, 0.0);
            out[0] = (float)(-v / N_OUT_D);
            gSum = 0.0;
            gCount = 0u;
            gMaxKey = 0u;
            gMinKey = 0xFFFFFFFFu;
        }
    }
}

extern "C" void kernel_launch(void* const* d_in, const int* in_sizes, int n_in,
                              void* d_out, int out_size) {
    const float* y_pred = (const float*)d_in[0];
    const float* y_true = (const float*)d_in[1];
    float* out = (float*)d_out;

    k_minmax<<<1024, 256>>>(y_pred, N_PIX / 4);

    cudaLaunchConfig_t cfg = {};
    cfg.gridDim = dim3(GRID_X, GRID_Y, N_IMG);
    cfg.blockDim = dim3(256, 1, 1);
    cfg.dynamicSmemBytes = 0;
    cudaLaunchAttribute attr[1];
    attr[0].id = cudaLaunchAttributeProgrammaticStreamSerialization;
    attr[0].val.programmaticStreamSerializationAllowed = 1;
    cfg.attrs = attr;
    cfg.numAttrs = 1;
    cudaLaunchKernelEx(&cfg, k_ssim, y_pred, y_true, out);
}